// round 5
// baseline (speedup 1.0000x reference)
#include <cuda_runtime.h>

typedef unsigned long long u64;
typedef unsigned int u32;

#define IMG_W 2048
#define IMG_H 2048
#define NWORDS 32               // 32 x u64 = 2048 bits per column
#define NPIX (IMG_W * IMG_H)
#define COFF 8                  // column padding: prefetch never bounds-checks
#define NCOLS (IMG_W + 2 * COFF)

// Interleaved bit grids, column-major: elem (c, w) = {A, L} for 64 rows.
// d_AL: canonical row order. d_ALr: reversed rows (brevll + word swap).
__device__ ulonglong2 d_AL [NCOLS * NWORDS];
__device__ ulonglong2 d_ALr[NCOLS * NWORDS];

__device__ __forceinline__ u32 redux_or(u32 v) {
    u32 r;
    asm("redux.sync.or.b32 %0, %1, 0xffffffff;" : "=r"(r) : "r"(v));
    return r;
}

// ---------------------------------------------------------------------------
// Fused: low/high outputs + bitpack {A = thin>=3, L = thin>=1}, both grids.
// ---------------------------------------------------------------------------
__global__ void k_prep(const float* __restrict__ thin, float* __restrict__ out) {
    int c = blockIdx.x * 32 + threadIdx.x;
    int w = blockIdx.y * blockDim.y + threadIdx.y;
    u64 L = 0, A = 0;
    size_t base = (size_t)(w * 64) * IMG_W + c;
    #pragma unroll 8
    for (int b = 0; b < 64; ++b) {
        size_t idx = base + (size_t)b * IMG_W;
        float v = thin[idx];
        bool lo = (v >= 1.0f), hi = (v >= 3.0f);
        out[idx]        = lo ? v : 0.0f;   // low
        out[NPIX + idx] = hi ? v : 0.0f;   // high
        L |= ((u64)lo) << b;
        A |= ((u64)hi) << b;
    }
    d_AL [(c + COFF) * NWORDS + w]        = make_ulonglong2(A, L);
    d_ALr[(c + COFF) * NWORDS + (31 - w)] = make_ulonglong2(__brevll(A), __brevll(L));
}

// ---------------------------------------------------------------------------
// One directional trace pass, single warp. Lane k owns 64 virtual rows in the
// stored orientation of the load grid (never any brev on loads).
// Gated-or scan s_i = g_i | (p_i & s_{i-1}) == carry chain of p+g (g subset p).
// Cross-lane carries: addc flags -> <<lane -> redux.or -> 32-bit scalar add.
// dn == cb; s == cb>>1 | cout<<63; mid = cb | cb>>2 | hi; side = mid | cb>>1 | hi.
// CROSS: store to the other grid at word 31-lane with brevll (off-chain).
// ---------------------------------------------------------------------------
template <bool XR, bool CROSS>
__device__ __forceinline__ void trace_pass(const int lane,
                                           const ulonglong2* __restrict__ ldb,
                                           u64* __restrict__ stb) {
    const u32 FULL = 0xffffffffu;
    u64 INTM = ~0ull;
    if (lane == 0)  INTM &= ~1ull;
    if (lane == 31) INTM &= 0x7fffffffffffffffull;
    const u32 notTop = (lane == 31) ? 0u : ~0u;

    const int dx = XR ? -1 : 1;
    const int cx0 = XR ? (IMG_W - 2) : 1;

    auto ld = [&](int c, u64& A, u64& L) {
        ulonglong2 v = ldb[(size_t)(c + COFF) * NWORDS];
        A = v.x; L = v.y;
    };
    auto st = [&](int c, u64 v) {
        stb[(size_t)(c + COFF) * NWORDS * 2] = CROSS ? __brevll(v) : v;
    };

    u64 Ap, Lp, Ac, Lc, An, Ln;
    ld(cx0 - dx, Ap, Lp);
    ld(cx0,      Ac, Lc);
    ld(cx0 + dx, An, Ln);
    u64 gc = Ac & INTM, pc = Lc & INTM;
    u64 Ab[6], Lb[6];
    #pragma unroll
    for (int j = 0; j < 6; ++j) ld(cx0 + (2 + j) * dx, Ab[j], Lb[j]);

    int cx = cx0;
    #pragma unroll 1
    for (int blk = 0; blk < (IMG_W - 2) / 6; ++blk) {      // 341 x 6 = 2046
        #pragma unroll
        for (int j = 0; j < 6; ++j) {
            // off-chain: next-lane bit0 info
            u32 b0 = ((u32)gc & 1u) | (((u32)pc << 1) & 2u);
            u32 b0n = __shfl_down_sync(FULL, b0, 1) & notTop;
            u64 pxg = pc ^ gc;
            // lane carry flags via HW carry
            u64 sum0, sum1; u32 cgen, cprop;
            asm("add.cc.u64 %0, %4, %5;\n\t"
                "addc.u32 %2, 0, 0;\n\t"
                "add.cc.u64 %1, %0, 1;\n\t"
                "addc.u32 %3, 0, 0;"
                : "=l"(sum0), "=l"(sum1), "=r"(cgen), "=r"(cprop)
                : "l"(pc), "l"(gc));
            u32 G = redux_or(cgen << lane);
            u32 P = redux_or(cprop << lane);
            u32 C = (P + G) ^ (P ^ G);        // carry-in per lane (bit32 provably 0)
            u32 Cs = C >> lane;               // bit0 = cin, bit1 = cout
            u32 cin = Cs & 1u;
            u64 cb = (sum0 + (u64)cin) ^ pxg; // carry-in bits == dn
            u64 t = cb | (cb >> 2);
            u32 co = Cs & 2u;
            u32 s0n = (b0n & 1u) | ((b0n >> 1) & (Cs >> 1) & 1u);
            u32 hm = (co << 29) | (s0n << 31);      // cout->bit62, s0n->bit63
            u32 hs = hm | (co << 30);               // + cout->bit63
            u64 mid  = t | ((u64)hm << 32);
            u64 side = t | (cb >> 1) | ((u64)hs << 32);

            st(cx - dx, Ap | (side & Lp));    // final for this pass
            Ap = Ac | (mid & Lc);  Lp = Lc;
            Ac = An | (side & Ln);
            gc = Ac & INTM;                   // critical recurrence
            pc = Ln & INTM;
            Lc = Ln;
            An = Ab[j]; Ln = Lb[j];
            ld(cx + 8 * dx, Ab[j], Lb[j]);    // padded: no bounds check
            cx += dx;
        }
    }
    st(cx - dx, Ap);
    st(cx, Ac);
}

__global__ void __launch_bounds__(32, 1) k_trace() {
    const int lane = threadIdx.x;
    // p1 (F,F): read AL,  write ALr (cross)
    trace_pass<false, true >(lane, d_AL  + lane, (u64*)(d_ALr + (31 - lane)));
    __threadfence_block(); __syncwarp();
    // p2 (T,T): read/write ALr
    trace_pass<true,  false>(lane, d_ALr + lane, (u64*)(d_ALr + lane));
    __threadfence_block(); __syncwarp();
    // p3 (F,T): read ALr, write AL (cross)
    trace_pass<false, true >(lane, d_ALr + lane, (u64*)(d_AL  + (31 - lane)));
    __threadfence_block(); __syncwarp();
    // p4 (T,F): read/write AL
    trace_pass<true,  false>(lane, d_AL  + lane, (u64*)(d_AL  + lane));
}

// ---------------------------------------------------------------------------
// final = A ? thin : 0. Tile 64 rows x 32 cols; thread owns one column-word,
// writes 8 coalesced pixels.
// ---------------------------------------------------------------------------
__global__ void k_final(const float* __restrict__ thin, float* __restrict__ out) {
    int c0 = blockIdx.x * 32;
    int r0 = blockIdx.y * 64;
    int lane = threadIdx.x & 31;
    int sub  = threadIdx.x >> 5;      // 0..7
    u64 wrd = d_AL[(c0 + lane + COFF) * NWORDS + (r0 >> 6)].x;
    #pragma unroll
    for (int k = 0; k < 8; ++k) {
        int rr = sub * 8 + k;
        size_t idx = (size_t)(r0 + rr) * IMG_W + c0 + lane;
        bool act = (wrd >> rr) & 1ull;
        out[2 * NPIX + idx] = act ? thin[idx] : 0.0f;
    }
}

// ---------------------------------------------------------------------------
extern "C" void kernel_launch(void* const* d_in, const int* in_sizes, int n_in,
                              void* d_out, int out_size) {
    const float* thin = (const float*)d_in[0];
    float* out = (float*)d_out;

    dim3 bpB(32, 8);
    dim3 bpG(IMG_W / 32, NWORDS / 8);
    k_prep<<<bpG, bpB>>>(thin, out);

    k_trace<<<1, 32>>>();

    dim3 fG(IMG_W / 32, IMG_H / 64);
    k_final<<<fG, 256>>>(thin, out);
}